// round 14
// baseline (speedup 1.0000x reference)
#include <cuda_runtime.h>
#include <cuda_bf16.h>
#include <cstdint>
#include <cstddef>

// ---------------- problem constants ----------------
#define Nn    32768
#define Dd    512
#define D2    1024
#define FIN   64
#define DOUT  128
#define EPS_MSG 1e-7f
#define EPS_LN  1e-5f

#define CHUNK_ROWS 512
#define NCHUNK (Nn / CHUNK_ROWS)   // 64

// ---------------- scratch (device globals; no allocation allowed) ----------------
__device__ float g_x[(size_t)Nn * Dd];
__device__ float g_z[(size_t)Nn * D2];
__device__ __nv_bfloat16 g_ah[(size_t)Nn * Dd];
__device__ __nv_bfloat16 g_al[(size_t)Nn * Dd];
__device__ __nv_bfloat16 g_zh[(size_t)Nn * D2];
__device__ __nv_bfloat16 g_zl[(size_t)Nn * D2];
#define OFF_ENC   0
#define OFF_W1_0  32768
#define OFF_W2_0  557056
#define OFF_W1_1  1081344
#define OFF_W2_1  1605632
#define OFF_WF    2129920
#define WTOT      2195456
__device__ __nv_bfloat16 g_wh[WTOT];
__device__ __nv_bfloat16 g_wl[WTOT];
__device__ float g_pm [NCHUNK * Dd];
__device__ float g_pse[NCHUNK * Dd];
__device__ float g_psm[NCHUNK * Dd];
__device__ float g_agg [Dd];
__device__ float g_bias1[D2];

// ---------------- PTX helpers ----------------
__device__ __forceinline__ uint32_t smem_u32(const void* p) {
    uint32_t a;
    asm("{ .reg .u64 t; cvta.to.shared.u64 t, %1; cvt.u32.u64 %0, t; }" : "=r"(a) : "l"(p));
    return a;
}

__device__ __forceinline__ void cpa16(uint32_t saddr, const void* gaddr) {
    asm volatile("cp.async.cg.shared.global [%0], [%1], 16;"
                 :: "r"(saddr), "l"(__cvta_generic_to_global(gaddr)));
}
#define CP_COMMIT() asm volatile("cp.async.commit_group;" ::: "memory")
#define CP_WAIT0()  asm volatile("cp.async.wait_group 0;" ::: "memory")

__device__ __forceinline__ void ldsm4(uint32_t& r0, uint32_t& r1, uint32_t& r2, uint32_t& r3,
                                      uint32_t addr) {
    asm volatile("ldmatrix.sync.aligned.m8n8.x4.shared.b16 {%0,%1,%2,%3}, [%4];"
                 : "=r"(r0), "=r"(r1), "=r"(r2), "=r"(r3) : "r"(addr));
}

__device__ __forceinline__ void mma16816(float* d, const uint32_t* a, const uint32_t* b) {
    asm volatile("mma.sync.aligned.m16n8k16.row.col.f32.bf16.bf16.f32 "
                 "{%0,%1,%2,%3}, {%4,%5,%6,%7}, {%8,%9}, {%0,%1,%2,%3};"
                 : "+f"(d[0]), "+f"(d[1]), "+f"(d[2]), "+f"(d[3])
                 : "r"(a[0]), "r"(a[1]), "r"(a[2]), "r"(a[3]), "r"(b[0]), "r"(b[1]));
}

#define SWZ(o) ((o) ^ (((o) >> 3) & 0x70))

// ---------------- split-bf16 tensor-core GEMM via mma.sync ----------------
// C[M,N] = (Ahi+Alo)[M,K] @ (Bhi+Blo)^T, B stored [N,K] K-major. (+bias, EPI=1: +Cin)
// CTA 128m x NTn x 64k, 256 thr, 8 warps (4m x NT/32 n), warp tile 32x32.
// 2-stage cp.async pipeline, one __syncthreads per chunk.
// Hoisted fragment addressing via XOR identity: base has bits5-6 clear, ko=kk*32 occupies
// bits5-6 (below the swizzle source bits 7-9), hence SWZ(base+ko) == SWZ(base) ^ ko.
template<int NT, int EPI>
__global__ void __launch_bounds__(256, 2)
hgemm_k(const __nv_bfloat16* __restrict__ Ahi, const __nv_bfloat16* __restrict__ Alo,
        const __nv_bfloat16* __restrict__ Bhi, const __nv_bfloat16* __restrict__ Blo,
        const float* __restrict__ bias, const float* __restrict__ Cin,
        float* __restrict__ C, int K, int N)
{
    constexpr int NWN = NT / 32;
    constexpr uint32_t STG = 32768u + (uint32_t)NT * 256u;

    extern __shared__ char sm[];
    const uint32_t sb = smem_u32(sm);
    const int tid = threadIdx.x;
    const int lane = tid & 31;
    const int wid = tid >> 5;
    const int wm = (wid / NWN) * 32;
    const int wn = (wid % NWN) * 32;
    const size_t rowBase = (size_t)blockIdx.y * 128;
    const int    colBase = blockIdx.x * NT;
    const int KC = K >> 6;

    const __nv_bfloat16* gAh = Ahi + rowBase * (size_t)K;
    const __nv_bfloat16* gAl = Alo + rowBase * (size_t)K;
    const __nv_bfloat16* gBh = Bhi + (size_t)colBase * K;
    const __nv_bfloat16* gBl = Blo + (size_t)colBase * K;

    // ---- hoisted loader offsets (per thread, constant across chunks) ----
    uint32_t soA[4]; int goA[4];
    #pragma unroll
    for (int i = 0; i < 4; ++i) {
        int id = tid + i * 256;
        int r = id >> 3, j = id & 7;
        soA[i] = SWZ((uint32_t)(r * 128 + j * 16));
        goA[i] = r * K + j * 8;
    }
    uint32_t soB[NT / 32]; int goB[NT / 32];
    #pragma unroll
    for (int i = 0; i < NT / 32; ++i) {
        int id = tid + i * 256;
        int r = id >> 3, j = id & 7;
        soB[i] = SWZ((uint32_t)(r * 128 + j * 16));
        goB[i] = r * K + j * 8;
    }
    // ---- hoisted fragment swizzled offsets (constant across chunks/kk) ----
    const int lr = lane & 15;
    const int lc = lane >> 4;
    uint32_t fA[2], fB[2];
    #pragma unroll
    for (int mt = 0; mt < 2; ++mt)
        fA[mt] = SWZ((uint32_t)((wm + mt * 16 + lr) * 128 + lc * 16));
    #pragma unroll
    for (int np = 0; np < 2; ++np)
        fB[np] = SWZ((uint32_t)((wn + np * 16 + lr) * 128 + lc * 16));

    float acc[2][4][4];
    #pragma unroll
    for (int i = 0; i < 2; ++i)
        #pragma unroll
        for (int j = 0; j < 4; ++j)
            #pragma unroll
            for (int q = 0; q < 4; ++q) acc[i][j][q] = 0.f;

    auto load_stage = [&](uint32_t base, int k0) {
        #pragma unroll
        for (int i = 0; i < 4; ++i) {
            cpa16(base + soA[i],           gAh + goA[i] + k0);
            cpa16(base + 16384u + soA[i],  gAl + goA[i] + k0);
        }
        #pragma unroll
        for (int i = 0; i < NT / 32; ++i) {
            cpa16(base + 32768u + soB[i],                        gBh + goB[i] + k0);
            cpa16(base + 32768u + (uint32_t)NT * 128u + soB[i],  gBl + goB[i] + k0);
        }
    };

    load_stage(sb, 0);
    CP_COMMIT();

    for (int c = 0; c < KC; ++c) {
        CP_WAIT0();
        __syncthreads();

        const uint32_t aAh = sb + (uint32_t)(c & 1) * STG;
        const uint32_t aAl = aAh + 16384u;
        const uint32_t aBh = aAh + 32768u;
        const uint32_t aBl = aBh + (uint32_t)NT * 128u;

        #pragma unroll
        for (int kk = 0; kk < 4; ++kk) {
            const uint32_t ko = (uint32_t)(kk * 32);   // XOR-apply (bits 5-6, disjoint from base)
            uint32_t ah[2][4], al[2][4], bh[4][2], bl[4][2];
            #pragma unroll
            for (int mt = 0; mt < 2; ++mt) {
                const uint32_t fo = fA[mt] ^ ko;
                ldsm4(ah[mt][0], ah[mt][1], ah[mt][2], ah[mt][3], aAh + fo);
                ldsm4(al[mt][0], al[mt][1], al[mt][2], al[mt][3], aAl + fo);
            }
            #pragma unroll
            for (int np = 0; np < 2; ++np) {
                const uint32_t fo = fB[np] ^ ko;
                uint32_t r0, r1, r2, r3;
                ldsm4(r0, r1, r2, r3, aBh + fo);
                bh[np * 2][0] = r0; bh[np * 2 + 1][0] = r1;
                bh[np * 2][1] = r2; bh[np * 2 + 1][1] = r3;
                ldsm4(r0, r1, r2, r3, aBl + fo);
                bl[np * 2][0] = r0; bl[np * 2 + 1][0] = r1;
                bl[np * 2][1] = r2; bl[np * 2 + 1][1] = r3;
            }
            #pragma unroll
            for (int mt = 0; mt < 2; ++mt)
                #pragma unroll
                for (int nt = 0; nt < 4; ++nt) {
                    mma16816(acc[mt][nt], ah[mt], bh[nt]);
                    mma16816(acc[mt][nt], ah[mt], bl[nt]);
                    mma16816(acc[mt][nt], al[mt], bh[nt]);
                }
            if (kk == 0 && c + 1 < KC) {
                load_stage(sb + (uint32_t)((c + 1) & 1) * STG, (c + 1) * 64);
                CP_COMMIT();
            }
        }
    }

    // ---------------- epilogue ----------------
    __syncthreads();
    const int l4 = lane >> 2;
    const int l2 = (lane & 3) * 2;
    float2 bv[4];
    #pragma unroll
    for (int nt = 0; nt < 4; ++nt)
        bv[nt] = *(const float2*)(bias + colBase + wn + nt * 8 + l2);

    #pragma unroll
    for (int mt = 0; mt < 2; ++mt) {
        const size_t m0 = rowBase + wm + mt * 16 + l4;
        #pragma unroll
        for (int nt = 0; nt < 4; ++nt) {
            const int n = colBase + wn + nt * 8 + l2;
            float2 o0, o1;
            o0.x = acc[mt][nt][0] + bv[nt].x; o0.y = acc[mt][nt][1] + bv[nt].y;
            o1.x = acc[mt][nt][2] + bv[nt].x; o1.y = acc[mt][nt][3] + bv[nt].y;
            if (EPI == 1) {
                float2 c0 = *(const float2*)(Cin + m0 * (size_t)N + n);
                float2 c1 = *(const float2*)(Cin + (m0 + 8) * (size_t)N + n);
                o0.x += c0.x; o0.y += c0.y;
                o1.x += c1.x; o1.y += c1.y;
            }
            *(float2*)(C + m0 * (size_t)N + n)       = o0;
            *(float2*)(C + (m0 + 8) * (size_t)N + n) = o1;
        }
    }
}

// ---------------- fp32 -> bf16 hi/lo split kernels ----------------
template<int RELU>
__global__ void conv_k(const float* __restrict__ src,
                       __nv_bfloat16* __restrict__ hi, __nv_bfloat16* __restrict__ lo,
                       int total4)
{
    int i = blockIdx.x * blockDim.x + threadIdx.x;
    if (i >= total4) return;
    float4 v = ((const float4*)src)[i];
    float a[4] = {v.x, v.y, v.z, v.w};
    if (RELU) {
        #pragma unroll
        for (int j = 0; j < 4; ++j) a[j] = fmaxf(a[j], 0.f);
    }
    unsigned short hb[4], lb[4];
    #pragma unroll
    for (int j = 0; j < 4; ++j) {
        __nv_bfloat16 h = __float2bfloat16_rn(a[j]);
        __nv_bfloat16 l = __float2bfloat16_rn(a[j] - __bfloat162float(h));
        hb[j] = __bfloat16_as_ushort(h);
        lb[j] = __bfloat16_as_ushort(l);
    }
    uint2 uh, ul;
    uh.x = (uint32_t)hb[0] | ((uint32_t)hb[1] << 16);
    uh.y = (uint32_t)hb[2] | ((uint32_t)hb[3] << 16);
    ul.x = (uint32_t)lb[0] | ((uint32_t)lb[1] << 16);
    ul.y = (uint32_t)lb[2] | ((uint32_t)lb[3] << 16);
    *(uint2*)(hi + (size_t)i * 4) = uh;
    *(uint2*)(lo + (size_t)i * 4) = ul;
}

// ---------------- weight transpose + split ----------------
__global__ void wtrans_k(const float* __restrict__ W,
                         __nv_bfloat16* __restrict__ Thi, __nv_bfloat16* __restrict__ Tlo,
                         int K, int N)
{
    __shared__ float tile[32][33];
    int k0 = blockIdx.y * 32, n0 = blockIdx.x * 32;
    int tx = threadIdx.x, ty = threadIdx.y;
    #pragma unroll
    for (int i = ty; i < 32; i += 8)
        tile[i][tx] = W[(size_t)(k0 + i) * N + n0 + tx];
    __syncthreads();
    #pragma unroll
    for (int i = ty; i < 32; i += 8) {
        float v = tile[tx][i];
        __nv_bfloat16 h = __float2bfloat16_rn(v);
        float r = v - __bfloat162float(h);
        size_t o = (size_t)(n0 + i) * K + k0 + tx;
        Thi[o] = h;
        Tlo[o] = __float2bfloat16_rn(r);
    }
}

// ---------------- single-pass online per-channel softmax-agg partials ----------------
__global__ void colagg_part_k(const float* __restrict__ x,
                              const float* __restrict__ tptr,
                              float* __restrict__ pm, float* __restrict__ pse,
                              float* __restrict__ psm)
{
    const float t = *tptr;
    const int cl = threadIdx.x & 63;
    const int lane = threadIdx.x >> 6;
    const int c = blockIdx.x * 64 + cl;
    const int r0 = blockIdx.y * CHUNK_ROWS;
    float m = -1e30f, se = 0.f, sm = 0.f;
    for (int r = r0 + lane; r < r0 + CHUNK_ROWS; r += 4) {
        float v = x[(size_t)r * Dd + c];
        float val = fmaxf(v, 0.f) + EPS_MSG;
        float a = t * val;
        if (a > m) {
            float sc = __expf(m - a);
            se *= sc; sm *= sc; m = a;
        }
        float e = __expf(a - m);
        se += e;
        sm = fmaf(e, val, sm);
    }
    __shared__ float s_m[256], s_se[256], s_sm[256];
    s_m[threadIdx.x] = m; s_se[threadIdx.x] = se; s_sm[threadIdx.x] = sm;
    __syncthreads();
    if (threadIdx.x < 64) {
        float M = s_m[cl];
        #pragma unroll
        for (int q = 1; q < 4; ++q) M = fmaxf(M, s_m[cl + q * 64]);
        float SE = 0.f, SM = 0.f;
        #pragma unroll
        for (int q = 0; q < 4; ++q) {
            float w = __expf(s_m[cl + q * 64] - M);
            SE = fmaf(s_se[cl + q * 64], w, SE);
            SM = fmaf(s_sm[cl + q * 64], w, SM);
        }
        pm [blockIdx.y * Dd + c] = M;
        pse[blockIdx.y * Dd + c] = SE;
        psm[blockIdx.y * Dd + c] = SM;
    }
}

__global__ void reduce_agg_k(const float* __restrict__ pm, const float* __restrict__ pse,
                             const float* __restrict__ psm, float* __restrict__ agg)
{
    int c = blockIdx.x * blockDim.x + threadIdx.x;
    if (c >= Dd) return;
    float M = -1e30f;
    #pragma unroll 4
    for (int ch = 0; ch < NCHUNK; ++ch) M = fmaxf(M, pm[ch * Dd + c]);
    float se = 0.f, sm = 0.f;
    #pragma unroll 4
    for (int ch = 0; ch < NCHUNK; ++ch) {
        float w = __expf(pm[ch * Dd + c] - M);
        se = fmaf(pse[ch * Dd + c], w, se);
        sm = fmaf(psm[ch * Dd + c], w, sm);
    }
    agg[c] = sm / se;
}

// ---------------- bias1c[n] = b1[n] + sum_k agg[k] * W1[k,n] ----------------
__global__ void gemv_bias_k(const __nv_bfloat16* __restrict__ twh,
                            const __nv_bfloat16* __restrict__ twl,
                            const float* __restrict__ b1, const float* __restrict__ agg,
                            float* __restrict__ out, int K)
{
    const int n = blockIdx.x * 8 + (threadIdx.x >> 5);
    const int lane = threadIdx.x & 31;
    const __nv_bfloat16* ph = twh + (size_t)n * K;
    const __nv_bfloat16* pl = twl + (size_t)n * K;
    float acc = 0.f;
    for (int k = lane; k < K; k += 32) {
        float w = __bfloat162float(ph[k]) + __bfloat162float(pl[k]);
        acc = fmaf(agg[k], w, acc);
    }
    #pragma unroll
    for (int o = 16; o; o >>= 1) acc += __shfl_xor_sync(0xffffffffu, acc, o);
    if (lane == 0) out[n] = b1[n] + acc;
}

// ---------------- fused LayerNorm + ReLU + bf16 split ----------------
__global__ void ln_relu_k(const float* __restrict__ z,
                          const float* __restrict__ gam, const float* __restrict__ bet,
                          __nv_bfloat16* __restrict__ zhi, __nv_bfloat16* __restrict__ zlo)
{
    __shared__ float2 sred[8];
    const size_t row = blockIdx.x;
    const float4* zr = (const float4*)(z + row * (size_t)D2);
    float4 v = zr[threadIdx.x];
    float s  = v.x + v.y + v.z + v.w;
    float ss = fmaf(v.x, v.x, fmaf(v.y, v.y, fmaf(v.z, v.z, v.w * v.w)));
    #pragma unroll
    for (int o = 16; o; o >>= 1) {
        s  += __shfl_xor_sync(0xffffffffu, s,  o);
        ss += __shfl_xor_sync(0xffffffffu, ss, o);
    }
    if ((threadIdx.x & 31) == 0) sred[threadIdx.x >> 5] = make_float2(s, ss);
    __syncthreads();
    float S = 0.f, SS = 0.f;
    #pragma unroll
    for (int i = 0; i < 8; ++i) { S += sred[i].x; SS += sred[i].y; }
    const float mu  = S * (1.f / 1024.f);
    const float var = SS * (1.f / 1024.f) - mu * mu;
    const float inv = rsqrtf(var + EPS_LN);
    const int c = threadIdx.x * 4;
    const float4 gg = *(const float4*)(gam + c);
    const float4 bb = *(const float4*)(bet + c);
    float a[4];
    a[0] = fmaxf(fmaf((v.x - mu) * inv, gg.x, bb.x), 0.f);
    a[1] = fmaxf(fmaf((v.y - mu) * inv, gg.y, bb.y), 0.f);
    a[2] = fmaxf(fmaf((v.z - mu) * inv, gg.z, bb.z), 0.f);
    a[3] = fmaxf(fmaf((v.w - mu) * inv, gg.w, bb.w), 0.f);
    unsigned short hb[4], lb[4];
    #pragma unroll
    for (int j = 0; j < 4; ++j) {
        __nv_bfloat16 h = __float2bfloat16_rn(a[j]);
        __nv_bfloat16 l = __float2bfloat16_rn(a[j] - __bfloat162float(h));
        hb[j] = __bfloat16_as_ushort(h);
        lb[j] = __bfloat16_as_ushort(l);
    }
    uint2 uh, ul;
    uh.x = (uint32_t)hb[0] | ((uint32_t)hb[1] << 16);
    uh.y = (uint32_t)hb[2] | ((uint32_t)hb[3] << 16);
    ul.x = (uint32_t)lb[0] | ((uint32_t)lb[1] << 16);
    ul.y = (uint32_t)lb[2] | ((uint32_t)lb[3] << 16);
    *(uint2*)(zhi + row * (size_t)D2 + c) = uh;
    *(uint2*)(zlo + row * (size_t)D2 + c) = ul;
}

// ---------------- host launcher ----------------
extern "C" void kernel_launch(void* const* d_in, const int* in_sizes, int n_in,
                              void* d_out, int out_size)
{
    const float* batch = (const float*)d_in[0];
    const float* W_enc = (const float*)d_in[1];
    const float* b_enc = (const float*)d_in[2];
    const float* Wf    = (const float*)d_in[3];
    const float* bf    = (const float*)d_in[4];
    const float* t [2] = {(const float*)d_in[5],  (const float*)d_in[12]};
    const float* W1[2] = {(const float*)d_in[6],  (const float*)d_in[13]};
    const float* b1[2] = {(const float*)d_in[7],  (const float*)d_in[14]};
    const float* g [2] = {(const float*)d_in[8],  (const float*)d_in[15]};
    const float* be[2] = {(const float*)d_in[9],  (const float*)d_in[16]};
    const float* W2[2] = {(const float*)d_in[10], (const float*)d_in[17]};
    const float* b2[2] = {(const float*)d_in[11], (const float*)d_in[18]};

    float *x, *z, *pm, *pse, *psm, *agg, *bias1;
    __nv_bfloat16 *ah, *al, *zh, *zl, *wh, *wl;
    cudaGetSymbolAddress((void**)&x,     g_x);
    cudaGetSymbolAddress((void**)&z,     g_z);
    cudaGetSymbolAddress((void**)&ah,    g_ah);
    cudaGetSymbolAddress((void**)&al,    g_al);
    cudaGetSymbolAddress((void**)&zh,    g_zh);
    cudaGetSymbolAddress((void**)&zl,    g_zl);
    cudaGetSymbolAddress((void**)&wh,    g_wh);
    cudaGetSymbolAddress((void**)&wl,    g_wl);
    cudaGetSymbolAddress((void**)&pm,    g_pm);
    cudaGetSymbolAddress((void**)&pse,   g_pse);
    cudaGetSymbolAddress((void**)&psm,   g_psm);
    cudaGetSymbolAddress((void**)&agg,   g_agg);
    cudaGetSymbolAddress((void**)&bias1, g_bias1);

    const int SMEM = 2 * (32768 + 64 * 256);   // 98304 -> 2 CTAs/SM
    cudaFuncSetAttribute((const void*)hgemm_k<64,0>, cudaFuncAttributeMaxDynamicSharedMemorySize, SMEM);
    cudaFuncSetAttribute((const void*)hgemm_k<64,1>, cudaFuncAttributeMaxDynamicSharedMemorySize, SMEM);

    // [1] encoder weights, [2] batch split, [3] filler wtrans, [4] encoder GEMM (profiled)
    wtrans_k<<<dim3(Dd/32,  FIN/32), dim3(32,8)>>>(W_enc, wh + OFF_ENC,  wl + OFF_ENC,  FIN, Dd);
    conv_k<0><<<(Nn * FIN / 4 + 255) / 256, 256>>>(batch, zh, zl, Nn * FIN / 4);
    wtrans_k<<<dim3(D2/32,  Dd/32),  dim3(32,8)>>>(W1[0], wh + OFF_W1_0, wl + OFF_W1_0, Dd,  D2);
    hgemm_k<64,0><<<dim3(Dd/64, Nn/128), 256, SMEM>>>(
        zh, zl, wh + OFF_ENC, wl + OFF_ENC, b_enc, nullptr, x, FIN, Dd);
    // remaining weight transposes
    wtrans_k<<<dim3(Dd/32,  D2/32),  dim3(32,8)>>>(W2[0], wh + OFF_W2_0, wl + OFF_W2_0, D2,  Dd);
    wtrans_k<<<dim3(D2/32,  Dd/32),  dim3(32,8)>>>(W1[1], wh + OFF_W1_1, wl + OFF_W1_1, Dd,  D2);
    wtrans_k<<<dim3(Dd/32,  D2/32),  dim3(32,8)>>>(W2[1], wh + OFF_W2_1, wl + OFF_W2_1, D2,  Dd);
    wtrans_k<<<dim3(DOUT/32, Dd/32), dim3(32,8)>>>(Wf,    wh + OFF_WF,   wl + OFF_WF,   Dd,  DOUT);

    const size_t woff1[2] = {OFF_W1_0, OFF_W1_1};
    const size_t woff2[2] = {OFF_W2_0, OFF_W2_1};
    const dim3 gCol(Dd / 64, NCHUNK);

    for (int l = 0; l < 2; ++l) {
        colagg_part_k<<<gCol, 256>>>(x, t[l], pm, pse, psm);
        reduce_agg_k <<<2, 256>>>(pm, pse, psm, agg);
        gemv_bias_k<<<D2/8, 256>>>(wh + woff1[l], wl + woff1[l], b1[l], agg, bias1, Dd);
        conv_k<1><<<Nn * Dd / 4 / 256, 256>>>(x, ah, al, Nn * Dd / 4);
        hgemm_k<64,0><<<dim3(D2/64, Nn/128), 256, SMEM>>>(
            ah, al, wh + woff1[l], wl + woff1[l], bias1, nullptr, z, Dd, D2);
        ln_relu_k<<<Nn, 256>>>(z, g[l], be[l], zh, zl);
        hgemm_k<64,1><<<dim3(Dd/64, Nn/128), 256, SMEM>>>(
            zh, zl, wh + woff2[l], wl + woff2[l], b2[l], x, x, D2, Dd);
    }

    // ---- final: out = relu(x) @ Wf + bf ----
    conv_k<1><<<Nn * Dd / 4 / 256, 256>>>(x, ah, al, Nn * Dd / 4);
    hgemm_k<64,0><<<dim3(DOUT/64, Nn/128), 256, SMEM>>>(
        ah, al, wh + OFF_WF, wl + OFF_WF, bf, nullptr, (float*)d_out, Dd, DOUT);
}

// round 15
// speedup vs baseline: 1.4987x; 1.4987x over previous
#include <cuda_runtime.h>
#include <cuda_bf16.h>
#include <cstdint>
#include <cstddef>

// ---------------- problem constants ----------------
#define Nn    32768
#define Dd    512
#define D2    1024
#define FIN   64
#define DOUT  128
#define EPS_MSG 1e-7f
#define EPS_LN  1e-5f

#define CHUNK_ROWS 512
#define NCHUNK (Nn / CHUNK_ROWS)   // 64

// ---------------- scratch (device globals; no allocation allowed) ----------------
__device__ float g_x[(size_t)Nn * Dd];
__device__ float g_z[(size_t)Nn * D2];
__device__ __nv_bfloat16 g_ah[(size_t)Nn * Dd];
__device__ __nv_bfloat16 g_al[(size_t)Nn * Dd];
__device__ __nv_bfloat16 g_zh[(size_t)Nn * D2];
__device__ __nv_bfloat16 g_zl[(size_t)Nn * D2];
#define OFF_ENC   0
#define OFF_W1_0  32768
#define OFF_W2_0  557056
#define OFF_W1_1  1081344
#define OFF_W2_1  1605632
#define OFF_WF    2129920
#define WTOT      2195456
__device__ __nv_bfloat16 g_wh[WTOT];
__device__ __nv_bfloat16 g_wl[WTOT];
__device__ float g_pm [NCHUNK * Dd];
__device__ float g_pse[NCHUNK * Dd];
__device__ float g_psm[NCHUNK * Dd];
__device__ float g_agg [Dd];
__device__ float g_bias1[D2];

// ---------------- PTX helpers ----------------
__device__ __forceinline__ uint32_t smem_u32(const void* p) {
    uint32_t a;
    asm("{ .reg .u64 t; cvta.to.shared.u64 t, %1; cvt.u32.u64 %0, t; }" : "=r"(a) : "l"(p));
    return a;
}

__device__ __forceinline__ void cpa16(uint32_t saddr, const void* gaddr) {
    asm volatile("cp.async.cg.shared.global [%0], [%1], 16;"
                 :: "r"(saddr), "l"(__cvta_generic_to_global(gaddr)));
}
#define CP_COMMIT() asm volatile("cp.async.commit_group;" ::: "memory")
#define CP_WAIT0()  asm volatile("cp.async.wait_group 0;" ::: "memory")

__device__ __forceinline__ void ldsm4(uint32_t& r0, uint32_t& r1, uint32_t& r2, uint32_t& r3,
                                      uint32_t addr) {
    asm volatile("ldmatrix.sync.aligned.m8n8.x4.shared.b16 {%0,%1,%2,%3}, [%4];"
                 : "=r"(r0), "=r"(r1), "=r"(r2), "=r"(r3) : "r"(addr));
}

__device__ __forceinline__ void mma16816(float* d, const uint32_t* a, const uint32_t* b) {
    asm volatile("mma.sync.aligned.m16n8k16.row.col.f32.bf16.bf16.f32 "
                 "{%0,%1,%2,%3}, {%4,%5,%6,%7}, {%8,%9}, {%0,%1,%2,%3};"
                 : "+f"(d[0]), "+f"(d[1]), "+f"(d[2]), "+f"(d[3])
                 : "r"(a[0]), "r"(a[1]), "r"(a[2]), "r"(a[3]), "r"(b[0]), "r"(b[1]));
}

#define SWZ(o) ((o) ^ (((o) >> 3) & 0x70))

// ---------------- stage loader: Ah/Al (128 rows) + Bh/Bl (NT rows), 64 bf16/row, 256 thr ----------------
template<int NT>
__device__ __forceinline__ void load_stage(uint32_t sbase, int s,
                                           const __nv_bfloat16* a0, const __nv_bfloat16* a1,
                                           const __nv_bfloat16* b0, const __nv_bfloat16* b1,
                                           int K, int k0, int tid)
{
    constexpr uint32_t STG = 32768u + (uint32_t)NT * 256u;
    const uint32_t base = sbase + (uint32_t)s * STG;
    #pragma unroll
    for (int i = 0; i < 4; ++i) {
        int id = tid + i * 256;
        int r = id >> 3, j = id & 7;
        uint32_t off = SWZ((uint32_t)(r * 128 + j * 16));
        const size_t go = (size_t)r * K + k0 + j * 8;
        cpa16(base + off,          a0 + go);
        cpa16(base + 16384u + off, a1 + go);
    }
    #pragma unroll
    for (int i = 0; i < NT / 32; ++i) {
        int id = tid + i * 256;
        int r = id >> 3, j = id & 7;
        uint32_t off = SWZ((uint32_t)(r * 128 + j * 16));
        const size_t go = (size_t)r * K + k0 + j * 8;
        cpa16(base + 32768u + off,                       b0 + go);
        cpa16(base + 32768u + (uint32_t)NT * 128u + off, b1 + go);
    }
}

// ---------------- split-bf16 tensor-core GEMM via mma.sync (R11-proven) ----------------
// C[M,N] = (Ahi+Alo)[M,K] @ (Bhi+Blo)^T, B stored [N,K] K-major. (+bias, EPI=1: +Cin)
// CTA 128m x NTn x 64k, 256 thr, 8 warps (4m x NT/32 n), warp tile 32x32.
// 2-stage cp.async pipeline, one __syncthreads per chunk.
template<int NT, int EPI>
__global__ void __launch_bounds__(256, 2)
hgemm_k(const __nv_bfloat16* __restrict__ Ahi, const __nv_bfloat16* __restrict__ Alo,
        const __nv_bfloat16* __restrict__ Bhi, const __nv_bfloat16* __restrict__ Blo,
        const float* __restrict__ bias, const float* __restrict__ Cin,
        float* __restrict__ C, int K, int N)
{
    constexpr int NWN = NT / 32;
    constexpr uint32_t STG = 32768u + (uint32_t)NT * 256u;

    extern __shared__ char sm[];
    const uint32_t sb = smem_u32(sm);
    const int tid = threadIdx.x;
    const int lane = tid & 31;
    const int wid = tid >> 5;
    const int wm = (wid / NWN) * 32;
    const int wn = (wid % NWN) * 32;
    const size_t rowBase = (size_t)blockIdx.y * 128;
    const int    colBase = blockIdx.x * NT;
    const int KC = K >> 6;

    const __nv_bfloat16* gAh = Ahi + rowBase * (size_t)K;
    const __nv_bfloat16* gAl = Alo + rowBase * (size_t)K;
    const __nv_bfloat16* gBh = Bhi + (size_t)colBase * K;
    const __nv_bfloat16* gBl = Blo + (size_t)colBase * K;

    float acc[2][4][4];
    #pragma unroll
    for (int i = 0; i < 2; ++i)
        #pragma unroll
        for (int j = 0; j < 4; ++j)
            #pragma unroll
            for (int q = 0; q < 4; ++q) acc[i][j][q] = 0.f;

    load_stage<NT>(sb, 0, gAh, gAl, gBh, gBl, K, 0, tid);
    CP_COMMIT();

    const int lr = lane & 15;
    const int lc = lane >> 4;

    for (int c = 0; c < KC; ++c) {
        CP_WAIT0();
        __syncthreads();

        const uint32_t aAh = sb + (uint32_t)(c & 1) * STG;
        const uint32_t aAl = aAh + 16384u;
        const uint32_t aBh = aAh + 32768u;
        const uint32_t aBl = aBh + (uint32_t)NT * 128u;

        #pragma unroll
        for (int kk = 0; kk < 4; ++kk) {
            uint32_t ah[2][4], al[2][4], bh[4][2], bl[4][2];
            #pragma unroll
            for (int mt = 0; mt < 2; ++mt) {
                uint32_t so = SWZ((uint32_t)((wm + mt * 16 + lr) * 128 + kk * 32 + lc * 16));
                ldsm4(ah[mt][0], ah[mt][1], ah[mt][2], ah[mt][3], aAh + so);
                ldsm4(al[mt][0], al[mt][1], al[mt][2], al[mt][3], aAl + so);
            }
            #pragma unroll
            for (int np = 0; np < 2; ++np) {
                uint32_t so = SWZ((uint32_t)((wn + np * 16 + lr) * 128 + kk * 32 + lc * 16));
                uint32_t r0, r1, r2, r3;
                ldsm4(r0, r1, r2, r3, aBh + so);
                bh[np * 2][0] = r0; bh[np * 2 + 1][0] = r1;
                bh[np * 2][1] = r2; bh[np * 2 + 1][1] = r3;
                ldsm4(r0, r1, r2, r3, aBl + so);
                bl[np * 2][0] = r0; bl[np * 2 + 1][0] = r1;
                bl[np * 2][1] = r2; bl[np * 2 + 1][1] = r3;
            }
            #pragma unroll
            for (int mt = 0; mt < 2; ++mt)
                #pragma unroll
                for (int nt = 0; nt < 4; ++nt) {
                    mma16816(acc[mt][nt], ah[mt], bh[nt]);
                    mma16816(acc[mt][nt], ah[mt], bl[nt]);
                    mma16816(acc[mt][nt], al[mt], bh[nt]);
                }
            if (kk == 0 && c + 1 < KC) {
                load_stage<NT>(sb, (c + 1) & 1, gAh, gAl, gBh, gBl, K, (c + 1) * 64, tid);
                CP_COMMIT();
            }
        }
    }

    // ---------------- epilogue ----------------
    __syncthreads();
    const int l4 = lane >> 2;
    const int l2 = (lane & 3) * 2;
    float2 bv[4];
    #pragma unroll
    for (int nt = 0; nt < 4; ++nt)
        bv[nt] = *(const float2*)(bias + colBase + wn + nt * 8 + l2);

    #pragma unroll
    for (int mt = 0; mt < 2; ++mt) {
        const size_t m0 = rowBase + wm + mt * 16 + l4;
        #pragma unroll
        for (int nt = 0; nt < 4; ++nt) {
            const int n = colBase + wn + nt * 8 + l2;
            float2 o0, o1;
            o0.x = acc[mt][nt][0] + bv[nt].x; o0.y = acc[mt][nt][1] + bv[nt].y;
            o1.x = acc[mt][nt][2] + bv[nt].x; o1.y = acc[mt][nt][3] + bv[nt].y;
            if (EPI == 1) {
                float2 c0 = *(const float2*)(Cin + m0 * (size_t)N + n);
                float2 c1 = *(const float2*)(Cin + (m0 + 8) * (size_t)N + n);
                o0.x += c0.x; o0.y += c0.y;
                o1.x += c1.x; o1.y += c1.y;
            }
            *(float2*)(C + m0 * (size_t)N + n)       = o0;
            *(float2*)(C + (m0 + 8) * (size_t)N + n) = o1;
        }
    }
}

// ---------------- fp32 -> bf16 hi/lo split kernels ----------------
template<int RELU>
__global__ void conv_k(const float* __restrict__ src,
                       __nv_bfloat16* __restrict__ hi, __nv_bfloat16* __restrict__ lo,
                       int total4)
{
    int i = blockIdx.x * blockDim.x + threadIdx.x;
    if (i >= total4) return;
    float4 v = ((const float4*)src)[i];
    float a[4] = {v.x, v.y, v.z, v.w};
    if (RELU) {
        #pragma unroll
        for (int j = 0; j < 4; ++j) a[j] = fmaxf(a[j], 0.f);
    }
    unsigned short hb[4], lb[4];
    #pragma unroll
    for (int j = 0; j < 4; ++j) {
        __nv_bfloat16 h = __float2bfloat16_rn(a[j]);
        __nv_bfloat16 l = __float2bfloat16_rn(a[j] - __bfloat162float(h));
        hb[j] = __bfloat16_as_ushort(h);
        lb[j] = __bfloat16_as_ushort(l);
    }
    uint2 uh, ul;
    uh.x = (uint32_t)hb[0] | ((uint32_t)hb[1] << 16);
    uh.y = (uint32_t)hb[2] | ((uint32_t)hb[3] << 16);
    ul.x = (uint32_t)lb[0] | ((uint32_t)lb[1] << 16);
    ul.y = (uint32_t)lb[2] | ((uint32_t)lb[3] << 16);
    *(uint2*)(hi + (size_t)i * 4) = uh;
    *(uint2*)(lo + (size_t)i * 4) = ul;
}

// ---------------- weight transpose + split ----------------
__global__ void wtrans_k(const float* __restrict__ W,
                         __nv_bfloat16* __restrict__ Thi, __nv_bfloat16* __restrict__ Tlo,
                         int K, int N)
{
    __shared__ float tile[32][33];
    int k0 = blockIdx.y * 32, n0 = blockIdx.x * 32;
    int tx = threadIdx.x, ty = threadIdx.y;
    #pragma unroll
    for (int i = ty; i < 32; i += 8)
        tile[i][tx] = W[(size_t)(k0 + i) * N + n0 + tx];
    __syncthreads();
    #pragma unroll
    for (int i = ty; i < 32; i += 8) {
        float v = tile[tx][i];
        __nv_bfloat16 h = __float2bfloat16_rn(v);
        float r = v - __bfloat162float(h);
        size_t o = (size_t)(n0 + i) * K + k0 + tx;
        Thi[o] = h;
        Tlo[o] = __float2bfloat16_rn(r);
    }
}

// ---------------- fused: online softmax-agg partials + split(relu(x)) emission ----------------
__global__ void colagg_part_k(const float* __restrict__ x,
                              const float* __restrict__ tptr,
                              float* __restrict__ pm, float* __restrict__ pse,
                              float* __restrict__ psm,
                              __nv_bfloat16* __restrict__ hi, __nv_bfloat16* __restrict__ lo)
{
    const float t = *tptr;
    const int cl = threadIdx.x & 63;
    const int lane = threadIdx.x >> 6;
    const int c = blockIdx.x * 64 + cl;
    const int r0 = blockIdx.y * CHUNK_ROWS;
    float m = -1e30f, se = 0.f, sm = 0.f;
    for (int r = r0 + lane; r < r0 + CHUNK_ROWS; r += 4) {
        const size_t idx = (size_t)r * Dd + c;
        float v = x[idx];
        float rl = fmaxf(v, 0.f);
        // emit split(relu(x)) for the GEMM1 A-operand (saves the separate conv pass)
        __nv_bfloat16 h = __float2bfloat16_rn(rl);
        __nv_bfloat16 l = __float2bfloat16_rn(rl - __bfloat162float(h));
        hi[idx] = h;
        lo[idx] = l;
        float val = rl + EPS_MSG;
        float a = t * val;
        if (a > m) {
            float sc = __expf(m - a);
            se *= sc; sm *= sc; m = a;
        }
        float e = __expf(a - m);
        se += e;
        sm = fmaf(e, val, sm);
    }
    __shared__ float s_m[256], s_se[256], s_sm[256];
    s_m[threadIdx.x] = m; s_se[threadIdx.x] = se; s_sm[threadIdx.x] = sm;
    __syncthreads();
    if (threadIdx.x < 64) {
        float M = s_m[cl];
        #pragma unroll
        for (int q = 1; q < 4; ++q) M = fmaxf(M, s_m[cl + q * 64]);
        float SE = 0.f, SM = 0.f;
        #pragma unroll
        for (int q = 0; q < 4; ++q) {
            float w = __expf(s_m[cl + q * 64] - M);
            SE = fmaf(s_se[cl + q * 64], w, SE);
            SM = fmaf(s_sm[cl + q * 64], w, SM);
        }
        pm [blockIdx.y * Dd + c] = M;
        pse[blockIdx.y * Dd + c] = SE;
        psm[blockIdx.y * Dd + c] = SM;
    }
}

__global__ void reduce_agg_k(const float* __restrict__ pm, const float* __restrict__ pse,
                             const float* __restrict__ psm, float* __restrict__ agg)
{
    int c = blockIdx.x * blockDim.x + threadIdx.x;
    if (c >= Dd) return;
    float M = -1e30f;
    #pragma unroll 4
    for (int ch = 0; ch < NCHUNK; ++ch) M = fmaxf(M, pm[ch * Dd + c]);
    float se = 0.f, sm = 0.f;
    #pragma unroll 4
    for (int ch = 0; ch < NCHUNK; ++ch) {
        float w = __expf(pm[ch * Dd + c] - M);
        se = fmaf(pse[ch * Dd + c], w, se);
        sm = fmaf(psm[ch * Dd + c], w, sm);
    }
    agg[c] = sm / se;
}

// ---------------- bias1c[n] = b1[n] + sum_k agg[k] * W1[k,n] ----------------
__global__ void gemv_bias_k(const __nv_bfloat16* __restrict__ twh,
                            const __nv_bfloat16* __restrict__ twl,
                            const float* __restrict__ b1, const float* __restrict__ agg,
                            float* __restrict__ out, int K)
{
    const int n = blockIdx.x * 8 + (threadIdx.x >> 5);
    const int lane = threadIdx.x & 31;
    const __nv_bfloat16* ph = twh + (size_t)n * K;
    const __nv_bfloat16* pl = twl + (size_t)n * K;
    float acc = 0.f;
    for (int k = lane; k < K; k += 32) {
        float w = __bfloat162float(ph[k]) + __bfloat162float(pl[k]);
        acc = fmaf(agg[k], w, acc);
    }
    #pragma unroll
    for (int o = 16; o; o >>= 1) acc += __shfl_xor_sync(0xffffffffu, acc, o);
    if (lane == 0) out[n] = b1[n] + acc;
}

// ---------------- fused LayerNorm + ReLU + bf16 split ----------------
__global__ void ln_relu_k(const float* __restrict__ z,
                          const float* __restrict__ gam, const float* __restrict__ bet,
                          __nv_bfloat16* __restrict__ zhi, __nv_bfloat16* __restrict__ zlo)
{
    __shared__ float2 sred[8];
    const size_t row = blockIdx.x;
    const float4* zr = (const float4*)(z + row * (size_t)D2);
    float4 v = zr[threadIdx.x];
    float s  = v.x + v.y + v.z + v.w;
    float ss = fmaf(v.x, v.x, fmaf(v.y, v.y, fmaf(v.z, v.z, v.w * v.w)));
    #pragma unroll
    for (int o = 16; o; o >>= 1) {
        s  += __shfl_xor_sync(0xffffffffu, s,  o);
        ss += __shfl_xor_sync(0xffffffffu, ss, o);
    }
    if ((threadIdx.x & 31) == 0) sred[threadIdx.x >> 5] = make_float2(s, ss);
    __syncthreads();
    float S = 0.f, SS = 0.f;
    #pragma unroll
    for (int i = 0; i < 8; ++i) { S += sred[i].x; SS += sred[i].y; }
    const float mu  = S * (1.f / 1024.f);
    const float var = SS * (1.f / 1024.f) - mu * mu;
    const float inv = rsqrtf(var + EPS_LN);
    const int c = threadIdx.x * 4;
    const float4 gg = *(const float4*)(gam + c);
    const float4 bb = *(const float4*)(bet + c);
    float a[4];
    a[0] = fmaxf(fmaf((v.x - mu) * inv, gg.x, bb.x), 0.f);
    a[1] = fmaxf(fmaf((v.y - mu) * inv, gg.y, bb.y), 0.f);
    a[2] = fmaxf(fmaf((v.z - mu) * inv, gg.z, bb.z), 0.f);
    a[3] = fmaxf(fmaf((v.w - mu) * inv, gg.w, bb.w), 0.f);
    unsigned short hb[4], lb[4];
    #pragma unroll
    for (int j = 0; j < 4; ++j) {
        __nv_bfloat16 h = __float2bfloat16_rn(a[j]);
        __nv_bfloat16 l = __float2bfloat16_rn(a[j] - __bfloat162float(h));
        hb[j] = __bfloat16_as_ushort(h);
        lb[j] = __bfloat16_as_ushort(l);
    }
    uint2 uh, ul;
    uh.x = (uint32_t)hb[0] | ((uint32_t)hb[1] << 16);
    uh.y = (uint32_t)hb[2] | ((uint32_t)hb[3] << 16);
    ul.x = (uint32_t)lb[0] | ((uint32_t)lb[1] << 16);
    ul.y = (uint32_t)lb[2] | ((uint32_t)lb[3] << 16);
    *(uint2*)(zhi + row * (size_t)D2 + c) = uh;
    *(uint2*)(zlo + row * (size_t)D2 + c) = ul;
}

// ---------------- host launcher ----------------
extern "C" void kernel_launch(void* const* d_in, const int* in_sizes, int n_in,
                              void* d_out, int out_size)
{
    const float* batch = (const float*)d_in[0];
    const float* W_enc = (const float*)d_in[1];
    const float* b_enc = (const float*)d_in[2];
    const float* Wf    = (const float*)d_in[3];
    const float* bf    = (const float*)d_in[4];
    const float* t [2] = {(const float*)d_in[5],  (const float*)d_in[12]};
    const float* W1[2] = {(const float*)d_in[6],  (const float*)d_in[13]};
    const float* b1[2] = {(const float*)d_in[7],  (const float*)d_in[14]};
    const float* g [2] = {(const float*)d_in[8],  (const float*)d_in[15]};
    const float* be[2] = {(const float*)d_in[9],  (const float*)d_in[16]};
    const float* W2[2] = {(const float*)d_in[10], (const float*)d_in[17]};
    const float* b2[2] = {(const float*)d_in[11], (const float*)d_in[18]};

    float *x, *z, *pm, *pse, *psm, *agg, *bias1;
    __nv_bfloat16 *ah, *al, *zh, *zl, *wh, *wl;
    cudaGetSymbolAddress((void**)&x,     g_x);
    cudaGetSymbolAddress((void**)&z,     g_z);
    cudaGetSymbolAddress((void**)&ah,    g_ah);
    cudaGetSymbolAddress((void**)&al,    g_al);
    cudaGetSymbolAddress((void**)&zh,    g_zh);
    cudaGetSymbolAddress((void**)&zl,    g_zl);
    cudaGetSymbolAddress((void**)&wh,    g_wh);
    cudaGetSymbolAddress((void**)&wl,    g_wl);
    cudaGetSymbolAddress((void**)&pm,    g_pm);
    cudaGetSymbolAddress((void**)&pse,   g_pse);
    cudaGetSymbolAddress((void**)&psm,   g_psm);
    cudaGetSymbolAddress((void**)&agg,   g_agg);
    cudaGetSymbolAddress((void**)&bias1, g_bias1);

    const int SMEM = 2 * (32768 + 64 * 256);   // 98304 -> 2 CTAs/SM
    cudaFuncSetAttribute((const void*)hgemm_k<64,0>, cudaFuncAttributeMaxDynamicSharedMemorySize, SMEM);
    cudaFuncSetAttribute((const void*)hgemm_k<64,1>, cudaFuncAttributeMaxDynamicSharedMemorySize, SMEM);

    // [1] encoder weights, [2] batch split, [3] filler wtrans, [4] encoder GEMM (profiled)
    wtrans_k<<<dim3(Dd/32,  FIN/32), dim3(32,8)>>>(W_enc, wh + OFF_ENC,  wl + OFF_ENC,  FIN, Dd);
    conv_k<0><<<(Nn * FIN / 4 + 255) / 256, 256>>>(batch, zh, zl, Nn * FIN / 4);
    wtrans_k<<<dim3(D2/32,  Dd/32),  dim3(32,8)>>>(W1[0], wh + OFF_W1_0, wl + OFF_W1_0, Dd,  D2);
    hgemm_k<64,0><<<dim3(Dd/64, Nn/128), 256, SMEM>>>(
        zh, zl, wh + OFF_ENC, wl + OFF_ENC, b_enc, nullptr, x, FIN, Dd);
    // remaining weight transposes
    wtrans_k<<<dim3(Dd/32,  D2/32),  dim3(32,8)>>>(W2[0], wh + OFF_W2_0, wl + OFF_W2_0, D2,  Dd);
    wtrans_k<<<dim3(D2/32,  Dd/32),  dim3(32,8)>>>(W1[1], wh + OFF_W1_1, wl + OFF_W1_1, Dd,  D2);
    wtrans_k<<<dim3(Dd/32,  D2/32),  dim3(32,8)>>>(W2[1], wh + OFF_W2_1, wl + OFF_W2_1, D2,  Dd);
    wtrans_k<<<dim3(DOUT/32, Dd/32), dim3(32,8)>>>(Wf,    wh + OFF_WF,   wl + OFF_WF,   Dd,  DOUT);

    const size_t woff1[2] = {OFF_W1_0, OFF_W1_1};
    const size_t woff2[2] = {OFF_W2_0, OFF_W2_1};
    const dim3 gCol(Dd / 64, NCHUNK);

    for (int l = 0; l < 2; ++l) {
        // fused: softmax-agg partials + split(relu(x)) -> ah/al
        colagg_part_k<<<gCol, 256>>>(x, t[l], pm, pse, psm, ah, al);
        reduce_agg_k <<<2, 256>>>(pm, pse, psm, agg);
        gemv_bias_k<<<D2/8, 256>>>(wh + woff1[l], wl + woff1[l], b1[l], agg, bias1, Dd);
        hgemm_k<64,0><<<dim3(D2/64, Nn/128), 256, SMEM>>>(
            ah, al, wh + woff1[l], wl + woff1[l], bias1, nullptr, z, Dd, D2);
        ln_relu_k<<<Nn, 256>>>(z, g[l], be[l], zh, zl);
        hgemm_k<64,1><<<dim3(Dd/64, Nn/128), 256, SMEM>>>(
            zh, zl, wh + woff2[l], wl + woff2[l], b2[l], x, x, D2, Dd);
    }

    // ---- final: out = relu(x) @ Wf + bf ----
    conv_k<1><<<Nn * Dd / 4 / 256, 256>>>(x, ah, al, Nn * Dd / 4);
    hgemm_k<64,0><<<dim3(DOUT/64, Nn/128), 256, SMEM>>>(
        ah, al, wh + OFF_WF, wl + OFF_WF, bf, nullptr, (float*)d_out, Dd, DOUT);
}

// round 16
// speedup vs baseline: 1.9899x; 1.3278x over previous
#include <cuda_runtime.h>
#include <cuda_bf16.h>
#include <cstdint>
#include <cstddef>

// ---------------- problem constants ----------------
#define Nn    32768
#define Dd    512
#define D2    1024
#define FIN   64
#define DOUT  128
#define EPS_MSG 1e-7f
#define EPS_LN  1e-5f

#define CHUNK_ROWS 512
#define NCHUNK (Nn / CHUNK_ROWS)   // 64

// ---------------- scratch (device globals; no allocation allowed) ----------------
__device__ float g_x[(size_t)Nn * Dd];     // fp32 residual stream
__device__ float g_z[(size_t)Nn * D2];     // fp32 hidden
__device__ float g_a[(size_t)Nn * D2];     // tf32-rounded fp32 A-operand buffer
// transposed tf32-rounded weights [N,K] fp32, packed at fixed offsets (element counts)
#define OFF_ENC   0
#define OFF_W1_0  32768
#define OFF_W2_0  557056
#define OFF_W1_1  1081344
#define OFF_W2_1  1605632
#define OFF_WF    2129920
#define WTOT      2195456
__device__ float g_wt[WTOT];
__device__ float g_pm [NCHUNK * Dd];
__device__ float g_pse[NCHUNK * Dd];
__device__ float g_psm[NCHUNK * Dd];
__device__ float g_agg [Dd];
__device__ float g_bias1[D2];

// ---------------- PTX helpers ----------------
__device__ __forceinline__ uint32_t smem_u32(const void* p) {
    uint32_t a;
    asm("{ .reg .u64 t; cvta.to.shared.u64 t, %1; cvt.u32.u64 %0, t; }" : "=r"(a) : "l"(p));
    return a;
}

__device__ __forceinline__ float tf32r(float x) {
    uint32_t u;
    asm("cvt.rna.tf32.f32 %0, %1;" : "=r"(u) : "f"(x));
    return __uint_as_float(u);
}

__device__ __forceinline__ void cpa16(uint32_t saddr, const void* gaddr) {
    asm volatile("cp.async.cg.shared.global [%0], [%1], 16;"
                 :: "r"(saddr), "l"(__cvta_generic_to_global(gaddr)));
}
#define CP_COMMIT() asm volatile("cp.async.commit_group;" ::: "memory")
#define CP_WAIT0()  asm volatile("cp.async.wait_group 0;" ::: "memory")

__device__ __forceinline__ void ldsm4(uint32_t& r0, uint32_t& r1, uint32_t& r2, uint32_t& r3,
                                      uint32_t addr) {
    asm volatile("ldmatrix.sync.aligned.m8n8.x4.shared.b16 {%0,%1,%2,%3}, [%4];"
                 : "=r"(r0), "=r"(r1), "=r"(r2), "=r"(r3) : "r"(addr));
}

__device__ __forceinline__ void mma_tf32(float* d, const uint32_t* a, const uint32_t* b) {
    asm volatile("mma.sync.aligned.m16n8k8.row.col.f32.tf32.tf32.f32 "
                 "{%0,%1,%2,%3}, {%4,%5,%6,%7}, {%8,%9}, {%0,%1,%2,%3};"
                 : "+f"(d[0]), "+f"(d[1]), "+f"(d[2]), "+f"(d[3])
                 : "r"(a[0]), "r"(a[1]), "r"(a[2]), "r"(a[3]), "r"(b[0]), "r"(b[1]));
}

// 256B-row swizzle: sources bits 8-10 (row), targets bits 4-6 (16B seg within 128B).
#define SWZ32(o) ((o) ^ (((o) >> 4) & 0x70))

// ---------------- tf32 tensor-core GEMM via mma.sync ----------------
// C[M,N] = A[M,K] @ B^T, B stored [N,K] K-major, operands tf32-rounded fp32.
// CTA 128m x 64n x 64k, 256 thr, 8 warps (4m x 2n), warp tile 32x32.
// 2-stage cp.async pipeline, one __syncthreads per chunk (R11 schedule).
// stage = A 32KB + B 16KB = 48KB; 2 stages = 96KB -> 2 CTAs/SM.
#define STG32 49152u
template<int EPI>
__global__ void __launch_bounds__(256, 2)
tgemm_k(const float* __restrict__ A, const float* __restrict__ B,
        const float* __restrict__ bias, const float* __restrict__ Cin,
        float* __restrict__ C, int K, int N)
{
    extern __shared__ char sm[];
    const uint32_t sb = smem_u32(sm);
    const int tid = threadIdx.x;
    const int lane = tid & 31;
    const int wid = tid >> 5;
    const int wm = (wid >> 1) * 32;
    const int wn = (wid & 1) * 32;
    const size_t rowBase = (size_t)blockIdx.y * 128;
    const int    colBase = blockIdx.x * 64;
    const int KC = K >> 6;

    const float* gA = A + rowBase * (size_t)K;
    const float* gB = B + (size_t)colBase * K;

    float acc[2][4][4];
    #pragma unroll
    for (int i = 0; i < 2; ++i)
        #pragma unroll
        for (int j = 0; j < 4; ++j)
            #pragma unroll
            for (int q = 0; q < 4; ++q) acc[i][j][q] = 0.f;

    auto load_stage = [&](uint32_t base, int k0) {
        #pragma unroll
        for (int i = 0; i < 8; ++i) {               // A: 128 rows x 16 segs
            int seg = tid + i * 256;
            int r = seg >> 4, s = seg & 15;
            uint32_t phys = (uint32_t)r * 256u + (((uint32_t)s * 16u) ^ (((uint32_t)(r & 7)) << 4));
            cpa16(base + phys, gA + (size_t)r * K + k0 + s * 4);
        }
        #pragma unroll
        for (int i = 0; i < 4; ++i) {               // B: 64 rows x 16 segs
            int seg = tid + i * 256;
            int r = seg >> 4, s = seg & 15;
            uint32_t phys = (uint32_t)r * 256u + (((uint32_t)s * 16u) ^ (((uint32_t)(r & 7)) << 4));
            cpa16(base + 32768u + phys, gB + (size_t)r * K + k0 + s * 4);
        }
    };

    load_stage(sb, 0);
    CP_COMMIT();

    // A fragment addressing: lanes 0-15 -> rows tile+0..15 at kb+0; lanes 16-31 same rows at kb+16
    const int lrA = lane & 15;
    const int lcA = lane >> 4;
    // B fragment addressing (x4 = two n8 tiles):
    //   nrow = wn + np*16 + ((lane>>4)&1)*8 + (lane&7);  kb += ((lane>>3)&1)*16
    const int nrOff = ((lane >> 4) & 1) * 8 + (lane & 7);
    const int kbOff = ((lane >> 3) & 1) * 16;

    for (int c = 0; c < KC; ++c) {
        CP_WAIT0();
        __syncthreads();

        const uint32_t aA = sb + (uint32_t)(c & 1) * STG32;
        const uint32_t aB = aA + 32768u;

        #pragma unroll
        for (int kk = 0; kk < 8; ++kk) {
            uint32_t af[2][4], bf[4][2];
            #pragma unroll
            for (int mt = 0; mt < 2; ++mt) {
                int row = wm + mt * 16 + lrA;
                uint32_t cb = (uint32_t)(kk * 32 + lcA * 16);
                uint32_t addr = aA + (uint32_t)row * 256u + (cb ^ (((uint32_t)(row & 7)) << 4));
                ldsm4(af[mt][0], af[mt][1], af[mt][2], af[mt][3], addr);
            }
            #pragma unroll
            for (int np = 0; np < 2; ++np) {
                int nrow = wn + np * 16 + nrOff;
                uint32_t kb = (uint32_t)(kk * 32 + kbOff);
                uint32_t addr = aB + (uint32_t)nrow * 256u + (kb ^ (((uint32_t)(nrow & 7)) << 4));
                uint32_t r0, r1, r2, r3;
                ldsm4(r0, r1, r2, r3, addr);
                bf[np * 2][0] = r0;     bf[np * 2][1] = r1;     // tile np*2:   b0,b1
                bf[np * 2 + 1][0] = r2; bf[np * 2 + 1][1] = r3; // tile np*2+1: b0,b1
            }
            #pragma unroll
            for (int mt = 0; mt < 2; ++mt)
                #pragma unroll
                for (int nt = 0; nt < 4; ++nt)
                    mma_tf32(acc[mt][nt], af[mt], bf[nt]);
            if (kk == 0 && c + 1 < KC) {
                load_stage(sb + (uint32_t)((c + 1) & 1) * STG32, (c + 1) * 64);
                CP_COMMIT();
            }
        }
    }

    // ---------------- epilogue ----------------
    __syncthreads();
    const int l4 = lane >> 2;
    const int l2 = (lane & 3) * 2;
    float2 bv[4];
    #pragma unroll
    for (int nt = 0; nt < 4; ++nt)
        bv[nt] = *(const float2*)(bias + colBase + wn + nt * 8 + l2);

    #pragma unroll
    for (int mt = 0; mt < 2; ++mt) {
        const size_t m0 = rowBase + wm + mt * 16 + l4;
        #pragma unroll
        for (int nt = 0; nt < 4; ++nt) {
            const int n = colBase + wn + nt * 8 + l2;
            float2 o0, o1;
            o0.x = acc[mt][nt][0] + bv[nt].x; o0.y = acc[mt][nt][1] + bv[nt].y;
            o1.x = acc[mt][nt][2] + bv[nt].x; o1.y = acc[mt][nt][3] + bv[nt].y;
            if (EPI == 1) {
                float2 c0 = *(const float2*)(Cin + m0 * (size_t)N + n);
                float2 c1 = *(const float2*)(Cin + (m0 + 8) * (size_t)N + n);
                o0.x += c0.x; o0.y += c0.y;
                o1.x += c1.x; o1.y += c1.y;
            }
            *(float2*)(C + m0 * (size_t)N + n)       = o0;
            *(float2*)(C + (m0 + 8) * (size_t)N + n) = o1;
        }
    }
}

// ---------------- fp32 -> tf32-rounded fp32 (optional relu) ----------------
template<int RELU>
__global__ void conv_k(const float* __restrict__ src, float* __restrict__ dst, int total4)
{
    int i = blockIdx.x * blockDim.x + threadIdx.x;
    if (i >= total4) return;
    float4 v = ((const float4*)src)[i];
    if (RELU) {
        v.x = fmaxf(v.x, 0.f); v.y = fmaxf(v.y, 0.f);
        v.z = fmaxf(v.z, 0.f); v.w = fmaxf(v.w, 0.f);
    }
    v.x = tf32r(v.x); v.y = tf32r(v.y); v.z = tf32r(v.z); v.w = tf32r(v.w);
    ((float4*)dst)[i] = v;
}

// ---------------- weight transpose + tf32 round: W[K,N] -> T[N,K] ----------------
__global__ void wtrans_k(const float* __restrict__ W, float* __restrict__ T, int K, int N)
{
    __shared__ float tile[32][33];
    int k0 = blockIdx.y * 32, n0 = blockIdx.x * 32;
    int tx = threadIdx.x, ty = threadIdx.y;
    #pragma unroll
    for (int i = ty; i < 32; i += 8)
        tile[i][tx] = W[(size_t)(k0 + i) * N + n0 + tx];
    __syncthreads();
    #pragma unroll
    for (int i = ty; i < 32; i += 8)
        T[(size_t)(n0 + i) * K + k0 + tx] = tf32r(tile[tx][i]);
}

// ---------------- fused: online softmax-agg partials + tf32(relu(x)) emission ----------------
__global__ void colagg_part_k(const float* __restrict__ x,
                              const float* __restrict__ tptr,
                              float* __restrict__ pm, float* __restrict__ pse,
                              float* __restrict__ psm, float* __restrict__ aout)
{
    const float t = *tptr;
    const int cl = threadIdx.x & 63;
    const int lane = threadIdx.x >> 6;
    const int c = blockIdx.x * 64 + cl;
    const int r0 = blockIdx.y * CHUNK_ROWS;
    float m = -1e30f, se = 0.f, sm = 0.f;
    for (int r = r0 + lane; r < r0 + CHUNK_ROWS; r += 4) {
        const size_t idx = (size_t)r * Dd + c;
        float v = x[idx];
        float rl = fmaxf(v, 0.f);
        aout[idx] = tf32r(rl);
        float val = rl + EPS_MSG;
        float a = t * val;
        if (a > m) {
            float sc = __expf(m - a);
            se *= sc; sm *= sc; m = a;
        }
        float e = __expf(a - m);
        se += e;
        sm = fmaf(e, val, sm);
    }
    __shared__ float s_m[256], s_se[256], s_sm[256];
    s_m[threadIdx.x] = m; s_se[threadIdx.x] = se; s_sm[threadIdx.x] = sm;
    __syncthreads();
    if (threadIdx.x < 64) {
        float M = s_m[cl];
        #pragma unroll
        for (int q = 1; q < 4; ++q) M = fmaxf(M, s_m[cl + q * 64]);
        float SE = 0.f, SM = 0.f;
        #pragma unroll
        for (int q = 0; q < 4; ++q) {
            float w = __expf(s_m[cl + q * 64] - M);
            SE = fmaf(s_se[cl + q * 64], w, SE);
            SM = fmaf(s_sm[cl + q * 64], w, SM);
        }
        pm [blockIdx.y * Dd + c] = M;
        pse[blockIdx.y * Dd + c] = SE;
        psm[blockIdx.y * Dd + c] = SM;
    }
}

__global__ void reduce_agg_k(const float* __restrict__ pm, const float* __restrict__ pse,
                             const float* __restrict__ psm, float* __restrict__ agg)
{
    int c = blockIdx.x * blockDim.x + threadIdx.x;
    if (c >= Dd) return;
    float M = -1e30f;
    #pragma unroll 4
    for (int ch = 0; ch < NCHUNK; ++ch) M = fmaxf(M, pm[ch * Dd + c]);
    float se = 0.f, sm = 0.f;
    #pragma unroll 4
    for (int ch = 0; ch < NCHUNK; ++ch) {
        float w = __expf(pm[ch * Dd + c] - M);
        se = fmaf(pse[ch * Dd + c], w, se);
        sm = fmaf(psm[ch * Dd + c], w, sm);
    }
    agg[c] = sm / se;
}

// ---------------- bias1c[n] = b1[n] + sum_k agg[k] * Wt[n,k] ----------------
__global__ void gemv_bias_k(const float* __restrict__ wt, const float* __restrict__ b1,
                            const float* __restrict__ agg, float* __restrict__ out, int K)
{
    const int n = blockIdx.x * 8 + (threadIdx.x >> 5);
    const int lane = threadIdx.x & 31;
    const float* p = wt + (size_t)n * K;
    float acc = 0.f;
    for (int k = lane; k < K; k += 32)
        acc = fmaf(agg[k], p[k], acc);
    #pragma unroll
    for (int o = 16; o; o >>= 1) acc += __shfl_xor_sync(0xffffffffu, acc, o);
    if (lane == 0) out[n] = b1[n] + acc;
}

// ---------------- fused LayerNorm + ReLU + tf32 round (row length 1024) ----------------
__global__ void ln_relu_k(const float* __restrict__ z,
                          const float* __restrict__ gam, const float* __restrict__ bet,
                          float* __restrict__ aout)
{
    __shared__ float2 sred[8];
    const size_t row = blockIdx.x;
    const float4* zr = (const float4*)(z + row * (size_t)D2);
    float4 v = zr[threadIdx.x];
    float s  = v.x + v.y + v.z + v.w;
    float ss = fmaf(v.x, v.x, fmaf(v.y, v.y, fmaf(v.z, v.z, v.w * v.w)));
    #pragma unroll
    for (int o = 16; o; o >>= 1) {
        s  += __shfl_xor_sync(0xffffffffu, s,  o);
        ss += __shfl_xor_sync(0xffffffffu, ss, o);
    }
    if ((threadIdx.x & 31) == 0) sred[threadIdx.x >> 5] = make_float2(s, ss);
    __syncthreads();
    float S = 0.f, SS = 0.f;
    #pragma unroll
    for (int i = 0; i < 8; ++i) { S += sred[i].x; SS += sred[i].y; }
    const float mu  = S * (1.f / 1024.f);
    const float var = SS * (1.f / 1024.f) - mu * mu;
    const float inv = rsqrtf(var + EPS_LN);
    const int c = threadIdx.x * 4;
    const float4 gg = *(const float4*)(gam + c);
    const float4 bb = *(const float4*)(bet + c);
    float4 o;
    o.x = tf32r(fmaxf(fmaf((v.x - mu) * inv, gg.x, bb.x), 0.f));
    o.y = tf32r(fmaxf(fmaf((v.y - mu) * inv, gg.y, bb.y), 0.f));
    o.z = tf32r(fmaxf(fmaf((v.z - mu) * inv, gg.z, bb.z), 0.f));
    o.w = tf32r(fmaxf(fmaf((v.w - mu) * inv, gg.w, bb.w), 0.f));
    *(float4*)(aout + row * (size_t)D2 + c) = o;
}

// ---------------- host launcher ----------------
extern "C" void kernel_launch(void* const* d_in, const int* in_sizes, int n_in,
                              void* d_out, int out_size)
{
    const float* batch = (const float*)d_in[0];
    const float* W_enc = (const float*)d_in[1];
    const float* b_enc = (const float*)d_in[2];
    const float* Wf    = (const float*)d_in[3];
    const float* bf    = (const float*)d_in[4];
    const float* t [2] = {(const float*)d_in[5],  (const float*)d_in[12]};
    const float* W1[2] = {(const float*)d_in[6],  (const float*)d_in[13]};
    const float* b1[2] = {(const float*)d_in[7],  (const float*)d_in[14]};
    const float* g [2] = {(const float*)d_in[8],  (const float*)d_in[15]};
    const float* be[2] = {(const float*)d_in[9],  (const float*)d_in[16]};
    const float* W2[2] = {(const float*)d_in[10], (const float*)d_in[17]};
    const float* b2[2] = {(const float*)d_in[11], (const float*)d_in[18]};

    float *x, *z, *a, *wt, *pm, *pse, *psm, *agg, *bias1;
    cudaGetSymbolAddress((void**)&x,     g_x);
    cudaGetSymbolAddress((void**)&z,     g_z);
    cudaGetSymbolAddress((void**)&a,     g_a);
    cudaGetSymbolAddress((void**)&wt,    g_wt);
    cudaGetSymbolAddress((void**)&pm,    g_pm);
    cudaGetSymbolAddress((void**)&pse,   g_pse);
    cudaGetSymbolAddress((void**)&psm,   g_psm);
    cudaGetSymbolAddress((void**)&agg,   g_agg);
    cudaGetSymbolAddress((void**)&bias1, g_bias1);

    const int SMEM = 2 * 49152;   // 98304 -> 2 CTAs/SM
    cudaFuncSetAttribute((const void*)tgemm_k<0>, cudaFuncAttributeMaxDynamicSharedMemorySize, SMEM);
    cudaFuncSetAttribute((const void*)tgemm_k<1>, cudaFuncAttributeMaxDynamicSharedMemorySize, SMEM);

    // [1] encoder weights, [2] batch cvt, [3] filler wtrans, [4] encoder GEMM (profiled)
    wtrans_k<<<dim3(Dd/32,  FIN/32), dim3(32,8)>>>(W_enc, wt + OFF_ENC, FIN, Dd);
    conv_k<0><<<(Nn * FIN / 4 + 255) / 256, 256>>>(batch, a, Nn * FIN / 4);
    wtrans_k<<<dim3(D2/32,  Dd/32),  dim3(32,8)>>>(W1[0], wt + OFF_W1_0, Dd, D2);
    tgemm_k<0><<<dim3(Dd/64, Nn/128), 256, SMEM>>>(a, wt + OFF_ENC, b_enc, nullptr, x, FIN, Dd);
    // remaining weight transposes
    wtrans_k<<<dim3(Dd/32,  D2/32),  dim3(32,8)>>>(W2[0], wt + OFF_W2_0, D2, Dd);
    wtrans_k<<<dim3(D2/32,  Dd/32),  dim3(32,8)>>>(W1[1], wt + OFF_W1_1, Dd, D2);
    wtrans_k<<<dim3(Dd/32,  D2/32),  dim3(32,8)>>>(W2[1], wt + OFF_W2_1, D2, Dd);
    wtrans_k<<<dim3(DOUT/32, Dd/32), dim3(32,8)>>>(Wf,    wt + OFF_WF,   Dd, DOUT);

    const size_t woff1[2] = {OFF_W1_0, OFF_W1_1};
    const size_t woff2[2] = {OFF_W2_0, OFF_W2_1};
    const dim3 gCol(Dd / 64, NCHUNK);

    for (int l = 0; l < 2; ++l) {
        // fused: softmax-agg partials + a = tf32(relu(x))
        colagg_part_k<<<gCol, 256>>>(x, t[l], pm, pse, psm, a);
        reduce_agg_k <<<2, 256>>>(pm, pse, psm, agg);
        gemv_bias_k<<<D2/8, 256>>>(wt + woff1[l], b1[l], agg, bias1, Dd);
        // z = a @ W1 + bias1c
        tgemm_k<0><<<dim3(D2/64, Nn/128), 256, SMEM>>>(a, wt + woff1[l], bias1, nullptr, z, Dd, D2);
        // a = tf32(relu(LN(z)))
        ln_relu_k<<<Nn, 256>>>(z, g[l], be[l], a);
        // x = x + a @ W2 + b2
        tgemm_k<1><<<dim3(Dd/64, Nn/128), 256, SMEM>>>(a, wt + woff2[l], b2[l], x, x, D2, Dd);
    }

    // ---- final: out = relu(x) @ Wf + bf ----
    conv_k<1><<<Nn * Dd / 4 / 256, 256>>>(x, a, Nn * Dd / 4);
    tgemm_k<0><<<dim3(DOUT/64, Nn/128), 256, SMEM>>>(a, wt + OFF_WF, bf, nullptr, (float*)d_out, Dd, DOUT);
}